// round 1
// baseline (speedup 1.0000x reference)
#include <cuda_runtime.h>
#include <math.h>

#define BB 8
#define SS 1024
#define DD 512
#define HH 8
#define HD 64
#define NROWS (BB*SS)      // 8192
#define EPSV 1e-5f
#define SCP 1032           // padded score row (floats)

// ---------------- scratch (device globals; no allocation allowed) ----------------
__device__ float g_Qp[NROWS*DD];
__device__ float g_Kp[NROWS*DD];
__device__ float g_Vp[NROWS*DD];
__device__ float g_ao[NROWS*DD];          // attn_out
__device__ float g_sum1[BB], g_sq1[BB], g_sum2[BB], g_sq2[BB];
__device__ float g_mean1[BB], g_rstd1[BB], g_mean2[BB], g_rstd2[BB];
__device__ int   g_cnt[BB];
__device__ int   g_mask[NROWS];

// ---------------- tiny kernels ----------------
__global__ void k_zero() {
    int t = threadIdx.x;
    if (t < BB) {
        g_sum1[t] = 0.f; g_sq1[t] = 0.f;
        g_sum2[t] = 0.f; g_sq2[t] = 0.f;
        g_cnt[t] = 0;
    }
}

// one block per row: row-valid mask + per-batch sum/sumsq of Q
__global__ void k_maskstats(const float* __restrict__ Q) {
    int row = blockIdx.x;
    int t = threadIdx.x;               // 128 threads, 4 floats each
    float4 q = ((const float4*)(Q + (size_t)row * DD))[t];
    bool nz = (q.x != 0.f) || (q.y != 0.f) || (q.z != 0.f) || (q.w != 0.f);
    float s  = q.x + q.y + q.z + q.w;
    float s2 = q.x*q.x + q.y*q.y + q.z*q.z + q.w*q.w;
    int valid = __syncthreads_or(nz ? 1 : 0);
    #pragma unroll
    for (int o = 16; o > 0; o >>= 1) {
        s  += __shfl_xor_sync(0xffffffffu, s,  o);
        s2 += __shfl_xor_sync(0xffffffffu, s2, o);
    }
    __shared__ float rs[4], rs2[4];
    if ((t & 31) == 0) { rs[t >> 5] = s; rs2[t >> 5] = s2; }
    __syncthreads();
    if (t == 0) {
        g_mask[row] = valid;
        if (valid) {
            int b = row >> 10;
            float ts  = rs[0] + rs[1] + rs[2] + rs[3];
            float ts2 = rs2[0] + rs2[1] + rs2[2] + rs2[3];
            atomicAdd(&g_cnt[b], 1);
            atomicAdd(&g_sum1[b], ts);
            atomicAdd(&g_sq1[b], ts2);
        }
    }
}

__global__ void k_final_stats(int which) {
    int b = threadIdx.x;
    if (b >= BB) return;
    float cntD = (float)g_cnt[b] * (float)DD;
    float sum = which ? g_sum2[b] : g_sum1[b];
    float sq  = which ? g_sq2[b]  : g_sq1[b];
    float mean = (cntD > 0.f) ? sum / cntD : 0.f;
    float var  = (cntD > 0.f) ? sq / cntD - mean * mean : 0.f;
    if (var < 0.f) var = 0.f;
    float rstd = rsqrtf(var + EPSV);
    if (which) { g_mean2[b] = mean; g_rstd2[b] = rstd; }
    else       { g_mean1[b] = mean; g_rstd1[b] = rstd; }
}

// ---------------- QKV GEMM: P = (norm(Q) @ W + b) * mask ----------------
// M=8192, N=512, K=512. BM=BN=128, BK=16, 256 thr, 8x8 per thread.
__global__ __launch_bounds__(256, 2)
void k_qkv(const float* __restrict__ Q,
           const float* __restrict__ Wq, const float* __restrict__ bq,
           const float* __restrict__ Wk, const float* __restrict__ bk,
           const float* __restrict__ Wv, const float* __restrict__ bv) {
    const float* Wm; const float* bias; float* out;
    int z = blockIdx.z;
    if (z == 0)      { Wm = Wq; bias = bq; out = g_Qp; }
    else if (z == 1) { Wm = Wk; bias = bk; out = g_Kp; }
    else             { Wm = Wv; bias = bv; out = g_Vp; }

    int n0 = blockIdx.x * 128, m0 = blockIdx.y * 128;
    int tid = threadIdx.x;
    int tx = tid & 15, ty = tid >> 4;

    __shared__ float As[16][132];
    __shared__ float Bs[16][128];
    __shared__ float maskS[128];

    int b = m0 >> 10;
    float mean = g_mean1[b], rstd = g_rstd1[b];
    if (tid < 128) maskS[tid] = g_mask[m0 + tid] ? rstd : 0.f;
    __syncthreads();

    float acc[8][8];
    #pragma unroll
    for (int i = 0; i < 8; i++)
        #pragma unroll
        for (int j = 0; j < 8; j++) acc[i][j] = 0.f;

    for (int k0 = 0; k0 < 512; k0 += 16) {
        #pragma unroll
        for (int i = 0; i < 2; i++) {
            int f = tid + 256 * i;
            int row = f >> 2, k4 = f & 3;
            float4 a = ((const float4*)(Q + (size_t)(m0 + row) * 512 + k0))[k4];
            float sc = maskS[row];
            As[4*k4+0][row] = (a.x - mean) * sc;
            As[4*k4+1][row] = (a.y - mean) * sc;
            As[4*k4+2][row] = (a.z - mean) * sc;
            As[4*k4+3][row] = (a.w - mean) * sc;
        }
        #pragma unroll
        for (int i = 0; i < 2; i++) {
            int f = tid + 256 * i;
            int kr = f >> 5, c4 = f & 31;
            ((float4*)Bs[kr])[c4] = ((const float4*)(Wm + (size_t)(k0 + kr) * 512 + n0))[c4];
        }
        __syncthreads();
        #pragma unroll
        for (int kk = 0; kk < 16; kk++) {
            float a[8], bb[8];
            *(float4*)&a[0]  = *(const float4*)&As[kk][ty * 8];
            *(float4*)&a[4]  = *(const float4*)&As[kk][ty * 8 + 4];
            *(float4*)&bb[0] = *(const float4*)&Bs[kk][tx * 8];
            *(float4*)&bb[4] = *(const float4*)&Bs[kk][tx * 8 + 4];
            #pragma unroll
            for (int i = 0; i < 8; i++)
                #pragma unroll
                for (int j = 0; j < 8; j++)
                    acc[i][j] += a[i] * bb[j];
        }
        __syncthreads();
    }

    #pragma unroll
    for (int i = 0; i < 8; i++) {
        int row = m0 + ty * 8 + i;
        bool msk = (maskS[ty * 8 + i] != 0.f);
        #pragma unroll
        for (int j4 = 0; j4 < 2; j4++) {
            int col = n0 + tx * 8 + j4 * 4;
            float4 o;
            if (msk) {
                o.x = acc[i][j4*4+0] + bias[col+0];
                o.y = acc[i][j4*4+1] + bias[col+1];
                o.z = acc[i][j4*4+2] + bias[col+2];
                o.w = acc[i][j4*4+3] + bias[col+3];
            } else { o.x = o.y = o.z = o.w = 0.f; }
            *(float4*)(out + (size_t)row * 512 + col) = o;
        }
    }
}

// ---------------- attention: scores -> softmax -> w out -> attn@V -> +Q -> stats2 ----------------
// grid (32, 64): 32 q-tiles of 32 rows, 64 (b,h). 256 threads.
__global__ __launch_bounds__(256)
void k_attn(const float* __restrict__ Q, float* __restrict__ w_out) {
    extern __shared__ float sm[];
    float* sc  = sm;                     // 32*1032
    float* kv  = sc + 32 * SCP;          // 128*65
    float* qs  = kv + 128 * 65;          // 32*65
    float* red = qs + 32 * 65;           // 16
    int*   qm  = (int*)(red + 16);       // 32
    int*   km  = qm + 32;                // 128

    int tid = threadIdx.x;
    int bh = blockIdx.y;
    int b = bh >> 3, h = bh & 7;
    int q0 = blockIdx.x * 32;
    size_t baseQ = ((size_t)b * SS + q0) * DD + h * HD;
    size_t baseK = ((size_t)b * SS) * DD + h * HD;

    // load q tile (32x64)
    #pragma unroll
    for (int i = 0; i < 2; i++) {
        int f = tid + 256 * i;
        int r = f >> 4, d4 = f & 15;
        float4 v = *(const float4*)(g_Qp + baseQ + (size_t)r * DD + d4 * 4);
        qs[r * 65 + d4 * 4 + 0] = v.x;
        qs[r * 65 + d4 * 4 + 1] = v.y;
        qs[r * 65 + d4 * 4 + 2] = v.z;
        qs[r * 65 + d4 * 4 + 3] = v.w;
    }
    if (tid < 32) qm[tid] = g_mask[b * SS + q0 + tid];
    __syncthreads();

    int tr = tid >> 5, tc = tid & 31;

    // ---- scores ----
    for (int kt = 0; kt < 8; kt++) {
        #pragma unroll
        for (int i = 0; i < 8; i++) {
            int f = tid + 256 * i;
            int r = f >> 4, d4 = f & 15;
            float4 v = *(const float4*)(g_Kp + baseK + (size_t)(kt * 128 + r) * DD + d4 * 4);
            kv[r * 65 + d4 * 4 + 0] = v.x;
            kv[r * 65 + d4 * 4 + 1] = v.y;
            kv[r * 65 + d4 * 4 + 2] = v.z;
            kv[r * 65 + d4 * 4 + 3] = v.w;
        }
        if (tid < 128) km[tid] = g_mask[b * SS + kt * 128 + tid];
        __syncthreads();

        float acc[4][4];
        #pragma unroll
        for (int i = 0; i < 4; i++)
            #pragma unroll
            for (int j = 0; j < 4; j++) acc[i][j] = 0.f;

        #pragma unroll
        for (int d = 0; d < 64; d++) {
            float a0 = qs[(tr*4+0)*65 + d];
            float a1 = qs[(tr*4+1)*65 + d];
            float a2 = qs[(tr*4+2)*65 + d];
            float a3 = qs[(tr*4+3)*65 + d];
            float c0 = kv[(tc*4+0)*65 + d];
            float c1 = kv[(tc*4+1)*65 + d];
            float c2 = kv[(tc*4+2)*65 + d];
            float c3 = kv[(tc*4+3)*65 + d];
            acc[0][0] += a0*c0; acc[0][1] += a0*c1; acc[0][2] += a0*c2; acc[0][3] += a0*c3;
            acc[1][0] += a1*c0; acc[1][1] += a1*c1; acc[1][2] += a1*c2; acc[1][3] += a1*c3;
            acc[2][0] += a2*c0; acc[2][1] += a2*c1; acc[2][2] += a2*c2; acc[2][3] += a2*c3;
            acc[3][0] += a3*c0; acc[3][1] += a3*c1; acc[3][2] += a3*c2; acc[3][3] += a3*c3;
        }
        #pragma unroll
        for (int i = 0; i < 4; i++) {
            int rr = tr * 4 + i;
            #pragma unroll
            for (int j = 0; j < 4; j++) {
                int cc = tc * 4 + j;
                sc[rr * SCP + kt * 128 + cc] = km[cc] ? acc[i][j] * 0.125f : -1e30f;
            }
        }
        __syncthreads();
    }

    // ---- softmax (8 threads per row) ----
    {
        int row = tid >> 3, l8 = tid & 7;
        float* srow = sc + row * SCP;
        float m = -1e30f;
        #pragma unroll 8
        for (int j = 0; j < 128; j++) m = fmaxf(m, srow[l8 + 8 * j]);
        m = fmaxf(m, __shfl_xor_sync(0xffffffffu, m, 1));
        m = fmaxf(m, __shfl_xor_sync(0xffffffffu, m, 2));
        m = fmaxf(m, __shfl_xor_sync(0xffffffffu, m, 4));
        float sum = 0.f;
        #pragma unroll 8
        for (int j = 0; j < 128; j++) {
            float p = __expf(srow[l8 + 8 * j] - m);
            srow[l8 + 8 * j] = p;
            sum += p;
        }
        sum += __shfl_xor_sync(0xffffffffu, sum, 1);
        sum += __shfl_xor_sync(0xffffffffu, sum, 2);
        sum += __shfl_xor_sync(0xffffffffu, sum, 4);
        float inv = qm[row] ? (1.0f / sum) : 0.f;
        #pragma unroll 8
        for (int j = 0; j < 128; j++) srow[l8 + 8 * j] *= inv;
    }
    __syncthreads();

    // ---- write w (coalesced float4) ----
    {
        size_t wbase = ((size_t)bh * SS + q0) * SS;
        #pragma unroll
        for (int i = 0; i < 32; i++) {
            int f = tid + 256 * i;
            int r = f >> 8, c4 = f & 255;
            *(float4*)(w_out + wbase + (size_t)r * SS + c4 * 4) =
                *(const float4*)&sc[r * SCP + c4 * 4];
        }
    }

    // ---- attn = w @ V ----
    int tr2 = tid >> 4, tc2 = tid & 15;
    float at[2][4];
    #pragma unroll
    for (int i = 0; i < 2; i++)
        #pragma unroll
        for (int j = 0; j < 4; j++) at[i][j] = 0.f;

    for (int vt = 0; vt < 8; vt++) {
        __syncthreads();
        #pragma unroll
        for (int i = 0; i < 8; i++) {
            int f = tid + 256 * i;
            int r = f >> 4, d4 = f & 15;
            float4 v = *(const float4*)(g_Vp + baseK + (size_t)(vt * 128 + r) * DD + d4 * 4);
            kv[r * 65 + d4 * 4 + 0] = v.x;
            kv[r * 65 + d4 * 4 + 1] = v.y;
            kv[r * 65 + d4 * 4 + 2] = v.z;
            kv[r * 65 + d4 * 4 + 3] = v.w;
        }
        __syncthreads();
        #pragma unroll 4
        for (int kk = 0; kk < 128; kk++) {
            float a0 = sc[(tr2*2+0) * SCP + vt * 128 + kk];
            float a1 = sc[(tr2*2+1) * SCP + vt * 128 + kk];
            float b0 = kv[kk * 65 + tc2 * 4 + 0];
            float b1 = kv[kk * 65 + tc2 * 4 + 1];
            float b2 = kv[kk * 65 + tc2 * 4 + 2];
            float b3 = kv[kk * 65 + tc2 * 4 + 3];
            at[0][0] += a0*b0; at[0][1] += a0*b1; at[0][2] += a0*b2; at[0][3] += a0*b3;
            at[1][0] += a1*b0; at[1][1] += a1*b1; at[1][2] += a1*b2; at[1][3] += a1*b3;
        }
    }

    // ---- epilogue: attn_out = attn + Q; stats2 accumulation ----
    float s1 = 0.f, s2 = 0.f;
    #pragma unroll
    for (int i = 0; i < 2; i++) {
        int r = tr2 * 2 + i;
        size_t g = ((size_t)b * SS + q0 + r) * DD + h * HD + tc2 * 4;
        float4 q4 = *(const float4*)(Q + g);
        float4 o;
        o.x = at[i][0] + q4.x;
        o.y = at[i][1] + q4.y;
        o.z = at[i][2] + q4.z;
        o.w = at[i][3] + q4.w;
        *(float4*)(g_ao + g) = o;
        s1 += o.x + o.y + o.z + o.w;
        s2 += o.x*o.x + o.y*o.y + o.z*o.z + o.w*o.w;
    }
    #pragma unroll
    for (int o = 16; o > 0; o >>= 1) {
        s1 += __shfl_xor_sync(0xffffffffu, s1, o);
        s2 += __shfl_xor_sync(0xffffffffu, s2, o);
    }
    int wid = tid >> 5;
    if ((tid & 31) == 0) { red[wid] = s1; red[8 + wid] = s2; }
    __syncthreads();
    if (tid == 0) {
        float S1 = 0.f, S2 = 0.f;
        #pragma unroll
        for (int i = 0; i < 8; i++) { S1 += red[i]; S2 += red[8 + i]; }
        atomicAdd(&g_sum2[b], S1);
        atomicAdd(&g_sq2[b], S2);
    }
}

// ---------------- output GEMM: out = ao + relu(norm2(ao) @ Wo + bo) ----------------
__global__ __launch_bounds__(256, 2)
void k_out(const float* __restrict__ Wo, const float* __restrict__ bo,
           float* __restrict__ out) {
    int n0 = blockIdx.x * 128, m0 = blockIdx.y * 128;
    int tid = threadIdx.x;
    int tx = tid & 15, ty = tid >> 4;

    __shared__ float As[16][132];
    __shared__ float Bs[16][128];
    __shared__ float maskS[128];

    int b = m0 >> 10;
    float mean = g_mean2[b], rstd = g_rstd2[b];
    if (tid < 128) maskS[tid] = g_mask[m0 + tid] ? rstd : 0.f;
    __syncthreads();

    float acc[8][8];
    #pragma unroll
    for (int i = 0; i < 8; i++)
        #pragma unroll
        for (int j = 0; j < 8; j++) acc[i][j] = 0.f;

    for (int k0 = 0; k0 < 512; k0 += 16) {
        #pragma unroll
        for (int i = 0; i < 2; i++) {
            int f = tid + 256 * i;
            int row = f >> 2, k4 = f & 3;
            float4 a = ((const float4*)(g_ao + (size_t)(m0 + row) * 512 + k0))[k4];
            float sc = maskS[row];
            As[4*k4+0][row] = (a.x - mean) * sc;
            As[4*k4+1][row] = (a.y - mean) * sc;
            As[4*k4+2][row] = (a.z - mean) * sc;
            As[4*k4+3][row] = (a.w - mean) * sc;
        }
        #pragma unroll
        for (int i = 0; i < 2; i++) {
            int f = tid + 256 * i;
            int kr = f >> 5, c4 = f & 31;
            ((float4*)Bs[kr])[c4] = ((const float4*)(Wo + (size_t)(k0 + kr) * 512 + n0))[c4];
        }
        __syncthreads();
        #pragma unroll
        for (int kk = 0; kk < 16; kk++) {
            float a[8], bb[8];
            *(float4*)&a[0]  = *(const float4*)&As[kk][ty * 8];
            *(float4*)&a[4]  = *(const float4*)&As[kk][ty * 8 + 4];
            *(float4*)&bb[0] = *(const float4*)&Bs[kk][tx * 8];
            *(float4*)&bb[4] = *(const float4*)&Bs[kk][tx * 8 + 4];
            #pragma unroll
            for (int i = 0; i < 8; i++)
                #pragma unroll
                for (int j = 0; j < 8; j++)
                    acc[i][j] += a[i] * bb[j];
        }
        __syncthreads();
    }

    #pragma unroll
    for (int i = 0; i < 8; i++) {
        int row = m0 + ty * 8 + i;
        #pragma unroll
        for (int j4 = 0; j4 < 2; j4++) {
            int col = n0 + tx * 8 + j4 * 4;
            float4 ao = *(const float4*)(g_ao + (size_t)row * 512 + col);
            float4 o;
            o.x = ao.x + fmaxf(acc[i][j4*4+0] + bo[col+0], 0.f);
            o.y = ao.y + fmaxf(acc[i][j4*4+1] + bo[col+1], 0.f);
            o.z = ao.z + fmaxf(acc[i][j4*4+2] + bo[col+2], 0.f);
            o.w = ao.w + fmaxf(acc[i][j4*4+3] + bo[col+3], 0.f);
            *(float4*)(out + (size_t)row * 512 + col) = o;
        }
    }
}

// ---------------- launch ----------------
extern "C" void kernel_launch(void* const* d_in, const int* in_sizes, int n_in,
                              void* d_out, int out_size) {
    const float* Q  = (const float*)d_in[0];
    const float* Wq = (const float*)d_in[1];
    const float* bq = (const float*)d_in[2];
    const float* Wk = (const float*)d_in[3];
    const float* bk = (const float*)d_in[4];
    const float* Wv = (const float*)d_in[5];
    const float* bv = (const float*)d_in[6];
    const float* Wo = (const float*)d_in[7];
    const float* bo = (const float*)d_in[8];

    float* out = (float*)d_out;
    float* w   = out + (size_t)BB * SS * DD;   // out first, then attention weights

    const int ATTN_SMEM = (32 * SCP + 128 * 65 + 32 * 65 + 16) * 4 + (32 + 128) * 4;
    cudaFuncSetAttribute(k_attn, cudaFuncAttributeMaxDynamicSharedMemorySize, ATTN_SMEM);

    k_zero<<<1, 32>>>();
    k_maskstats<<<NROWS, 128>>>(Q);
    k_final_stats<<<1, 8>>>(0);
    k_qkv<<<dim3(4, 64, 3), 256>>>(Q, Wq, bq, Wk, bk, Wv, bv);
    k_attn<<<dim3(32, 64), 256, ATTN_SMEM>>>(Q, w);
    k_final_stats<<<1, 8>>>(1);
    k_out<<<dim3(4, 64), 256>>>(Wo, bo, out);
}